// round 10
// baseline (speedup 1.0000x reference)
#include <cuda_runtime.h>
#include <math_constants.h>

// Density-aware Chamfer loss, B=4, N=8192, 3D fp32.
// R10: x-bin-sorted clouds + pruned scan on the validated R2 packed engine.
//  sort_kernel      : per cloud (8): stable counting sort by x-bin (256 bins),
//                     deterministic (chunk order + lanemask rank). Also zeroes
//                     g_cnt. Outputs g_sorted (x,y,z,|r|^2) + g_sidx.
//  nn_kernel        : sorted ref cloud in smem (jj-interleaved) + orig idx +
//                     group/supergroup x-bounds. Queries in sorted order.
//                     Home-range init, then ascending sweep with warp-vote
//                     x-bound pruning (inclusive compare + margin: ties safe).
//                     Packed fma.rn.f32x2 body identical to R2. Winning-group
//                     bit-exact rescan -> min ORIGINAL index among t==best.
//  finalize_partial : 256-block gather/exp/weight partial sums
//  finalize_final   : fixed-order merge -> out[b]

#define B_CONST   4
#define N_CONST   8192
#define NCLOUD    8
#define NBINS     256

#define TPB       256
#define QPT       2
#define QPC       (TPB * QPT)          // 512 queries / CTA
#define QCHUNKS   (N_CONST / QPC)      // 16
#define GROUP     32
#define JPG       (GROUP / 2)          // 16
#define NGROUPS   (N_CONST / GROUP)    // 256
#define NSUPER    (NGROUPS / 8)        // 32

#define FIN_TPB   256
#define FIN_BLOCKS (2 * B_CONST * N_CONST / FIN_TPB)  // 256
#define FIN_CPD   (N_CONST / FIN_TPB)                 // 32

#define SORT_SMEM (N_CONST * 16 + 2 * NBINS * 4)                     // 133120
#define NN_SMEM   ((32768 + 8192 + 2 * NGROUPS + 2 * NSUPER) * 4)    // 166144

__device__ float4 g_sorted[NCLOUD * N_CONST];
__device__ int    g_sidx  [NCLOUD * N_CONST];
__device__ int    g_idx   [2 * B_CONST * N_CONST];
__device__ int    g_cnt   [2 * B_CONST * N_CONST];
__device__ float  g_part  [FIN_BLOCKS];

__device__ __forceinline__ int bin_of(float x) {
    int bi = (int)floorf((x + 5.2f) * (256.0f / 10.4f));
    return min(max(bi, 0), NBINS - 1);
}

// cloud 0..3 = gts[b], cloud 4..7 = preds[b]
__global__ __launch_bounds__(512, 1) void sort_kernel(const float* __restrict__ gts,
                                                      const float* __restrict__ preds) {
    extern __shared__ char sm_raw[];
    float4* s_pts = (float4*)sm_raw;
    int* s_hist = (int*)(sm_raw + N_CONST * 16);
    int* s_base = s_hist + NBINS;
    const int tid = threadIdx.x;
    const int cloud = blockIdx.x;
    const float* src = (cloud < 4) ? gts + (long)cloud * N_CONST * 3
                                   : preds + (long)(cloud - 4) * N_CONST * 3;

    for (int i = tid; i < N_CONST; i += 512) g_cnt[cloud * N_CONST + i] = 0;
    if (tid < NBINS) s_hist[tid] = 0;
    for (int i = tid; i < N_CONST; i += 512) {
        float x = src[3 * i], y = src[3 * i + 1], z = src[3 * i + 2];
        s_pts[i] = make_float4(x, y, z, x * x + y * y + z * z);
    }
    __syncthreads();
    for (int i = tid; i < N_CONST; i += 512)
        atomicAdd(&s_hist[bin_of(s_pts[i].x)], 1);
    __syncthreads();
    if (tid == 0) {
        int run = 0;
        for (int bb = 0; bb < NBINS; bb++) { s_base[bb] = run; run += s_hist[bb]; }
    }
    __syncthreads();
    // Stable scatter: single warp, chunks in index order, lanemask rank.
    if (tid < 32) {
        for (int chunk = 0; chunk < N_CONST / 32; chunk++) {
            int i = chunk * 32 + tid;
            float4 p = s_pts[i];
            int bi = bin_of(p.x);
            unsigned mask = __match_any_sync(0xffffffffu, bi);
            int rank = __popc(mask & ((1u << tid) - 1u));
            int pos = s_base[bi] + rank;
            g_sorted[cloud * N_CONST + pos] = p;
            g_sidx[cloud * N_CONST + pos] = i;
            if ((int)(__ffs(mask) - 1) == tid) s_base[bi] += __popc(mask);
            __syncwarp();
        }
    }
}

// Packed body: identical math to R2 (bit-exact with rescan).
#define NN_BODY(G)                                                              \
    {                                                                           \
        const float* gb = s_tile + (G) * (JPG * 8);                             \
        float mE0 = CUDART_INF_F, mO0 = CUDART_INF_F;                           \
        float mE1 = CUDART_INF_F, mO1 = CUDART_INF_F;                           \
        _Pragma("unroll")                                                       \
        for (int jj = 0; jj < JPG; jj++) {                                      \
            ulonglong2 A  = *(const ulonglong2*)(gb + jj * 8);                  \
            ulonglong2 Bv = *(const ulonglong2*)(gb + jj * 8 + 4);              \
            float tlo, thi;                                                     \
            asm("{\n\t.reg .b64 t;\n\t"                                         \
                "fma.rn.f32x2 t, %2, %3, %4;\n\t"                               \
                "fma.rn.f32x2 t, %5, %6, t;\n\t"                                \
                "fma.rn.f32x2 t, %7, %8, t;\n\t"                                \
                "mov.b64 {%0, %1}, t;\n\t}"                                     \
                : "=f"(tlo), "=f"(thi)                                          \
                : "l"(qx2[0]), "l"(A.x), "l"(Bv.y),                             \
                  "l"(qy2[0]), "l"(A.y), "l"(qz2[0]), "l"(Bv.x));               \
            mE0 = fminf(mE0, tlo); mO0 = fminf(mO0, thi);                       \
            asm("{\n\t.reg .b64 t;\n\t"                                         \
                "fma.rn.f32x2 t, %2, %3, %4;\n\t"                               \
                "fma.rn.f32x2 t, %5, %6, t;\n\t"                                \
                "fma.rn.f32x2 t, %7, %8, t;\n\t"                                \
                "mov.b64 {%0, %1}, t;\n\t}"                                     \
                : "=f"(tlo), "=f"(thi)                                          \
                : "l"(qx2[1]), "l"(A.x), "l"(Bv.y),                             \
                  "l"(qy2[1]), "l"(A.y), "l"(qz2[1]), "l"(Bv.x));               \
            mE1 = fminf(mE1, tlo); mO1 = fminf(mO1, thi);                       \
        }                                                                       \
        float m0 = fminf(mE0, mO0);                                             \
        if (m0 < best[0]) { best[0] = m0; gidw[0] = (G); bestd[0] = m0 + cc[0]; } \
        float m1 = fminf(mE1, mO1);                                             \
        if (m1 < best[1]) { best[1] = m1; gidw[1] = (G); bestd[1] = m1 + cc[1]; } \
    }

// db = dir*B + b.  dir 0: queries = gts, refs = preds. dir 1: swapped.
__global__ __launch_bounds__(TPB, 1) void nn_kernel(const float* __restrict__ gts,
                                                    const float* __restrict__ preds) {
    extern __shared__ float sm[];
    float* s_tile = sm;                         // 32768 floats, jj-interleaved
    int*   s_sidx = (int*)(sm + 32768);         // 8192 orig indices
    float* s_glo  = sm + 32768 + 8192;          // 256
    float* s_ghi  = s_glo + NGROUPS;            // 256
    float* s_slo  = s_ghi + NGROUPS;            // 32
    float* s_shi  = s_slo + NSUPER;             // 32

    const int tid = threadIdx.x;
    const int db  = blockIdx.y;
    const int b   = db & 3;
    const int dir = db >> 2;
    const int qc  = (dir == 0) ? b : 4 + b;
    const int rc  = (dir == 0) ? 4 + b : b;
    const float4* gr  = g_sorted + rc * N_CONST;
    const int*    gri = g_sidx   + rc * N_CONST;
    const float4* gq  = g_sorted + qc * N_CONST;
    const int*    gqi = g_sidx   + qc * N_CONST;

    for (int j = tid; j < N_CONST; j += TPB) {
        float4 p = gr[j];
        int jj = j >> 1, h = j & 1;
        float* pp = s_tile + jj * 8;
        pp[0 + h] = p.x; pp[2 + h] = p.y; pp[4 + h] = p.z; pp[6 + h] = p.w;
        s_sidx[j] = gri[j];
    }
    __syncthreads();
    if (tid < NGROUPS) {
        float lo = CUDART_INF_F, hi = -CUDART_INF_F;
        for (int j = 0; j < GROUP; j++) {
            int pos = tid * GROUP + j;
            float x = s_tile[(pos >> 1) * 8 + (pos & 1)];
            lo = fminf(lo, x); hi = fmaxf(hi, x);
        }
        s_glo[tid] = lo; s_ghi[tid] = hi;
    }
    __syncthreads();
    if (tid < NSUPER) {
        float lo = CUDART_INF_F, hi = -CUDART_INF_F;
        for (int g = tid * 8; g < tid * 8 + 8; g++) {
            lo = fminf(lo, s_glo[g]); hi = fmaxf(hi, s_ghi[g]);
        }
        s_slo[tid] = lo; s_shi[tid] = hi;
    }
    __syncthreads();

    float qx[QPT], cc[QPT], qxs[QPT], qys[QPT], qzs[QPT];
    unsigned long long qx2[QPT], qy2[QPT], qz2[QPT];
    float best[QPT], bestd[QPT];
    int gidw[QPT], oq[QPT], ghome[QPT];

    #pragma unroll
    for (int k = 0; k < QPT; k++) {
        int qpos = blockIdx.x * QPC + tid * QPT + k;   // warp covers 64 sorted-adjacent queries
        float4 qp = gq[qpos];
        oq[k] = gqi[qpos];
        qx[k] = qp.x; cc[k] = qp.w;
        qxs[k] = -2.0f * qp.x; qys[k] = -2.0f * qp.y; qzs[k] = -2.0f * qp.z;
        asm("mov.b64 %0, {%1, %1};" : "=l"(qx2[k]) : "f"(qxs[k]));
        asm("mov.b64 %0, {%1, %1};" : "=l"(qy2[k]) : "f"(qys[k]));
        asm("mov.b64 %0, {%1, %1};" : "=l"(qz2[k]) : "f"(qzs[k]));
        best[k] = CUDART_INF_F; bestd[k] = CUDART_INF_F; gidw[k] = 0;
        int lo = 0, hi = NGROUPS - 1;
        #pragma unroll
        for (int it = 0; it < 8; it++) {
            int mid = (lo + hi + 1) >> 1;
            if (s_glo[mid] <= qx[k]) lo = mid; else hi = mid - 1;
        }
        ghome[k] = lo;
    }

    // warp-uniform init range
    int gmn = min(ghome[0], ghome[1]);
    int gmx = max(ghome[0], ghome[1]);
    #pragma unroll
    for (int o = 16; o; o >>= 1) {
        gmn = min(gmn, __shfl_xor_sync(0xffffffffu, gmn, o));
        gmx = max(gmx, __shfl_xor_sync(0xffffffffu, gmx, o));
    }
    for (int g = gmn; g <= gmx; g++) NN_BODY(g);

    // ascending pruned sweep (inclusive compares + margin: exact ties never lost)
    for (int s = 0; s < NSUPER; s++) {
        float dl0 = qx[0] - s_shi[s], dr0 = s_slo[s] - qx[0];
        float dd0 = fmaxf(fmaxf(dl0, dr0), 0.0f);
        float dl1 = qx[1] - s_shi[s], dr1 = s_slo[s] - qx[1];
        float dd1 = fmaxf(fmaxf(dl1, dr1), 0.0f);
        bool nd = (dd0 * dd0 <= bestd[0] * 1.000002f + 1e-7f)
               || (dd1 * dd1 <= bestd[1] * 1.000002f + 1e-7f);
        if (!__any_sync(0xffffffffu, nd)) continue;
        for (int g = s * 8; g < s * 8 + 8; g++) {
            if (g >= gmn && g <= gmx) continue;   // already processed
            float el0 = qx[0] - s_ghi[g], er0 = s_glo[g] - qx[0];
            float ee0 = fmaxf(fmaxf(el0, er0), 0.0f);
            float el1 = qx[1] - s_ghi[g], er1 = s_glo[g] - qx[1];
            float ee1 = fmaxf(fmaxf(el1, er1), 0.0f);
            bool gn = (ee0 * ee0 <= bestd[0] * 1.000002f + 1e-7f)
                   || (ee1 * ee1 <= bestd[1] * 1.000002f + 1e-7f);
            if (!__any_sync(0xffffffffu, gn)) continue;
            NN_BODY(g);
        }
    }

    // rescan winning group: bit-exact recompute, min ORIGINAL index among ties
    #pragma unroll
    for (int k = 0; k < QPT; k++) {
        const int base = gidw[k] * GROUP;
        int bi = 0x7fffffff;
        #pragma unroll 8
        for (int j = 0; j < GROUP; j++) {
            int pos = base + j;
            const float* p = s_tile + (pos >> 1) * 8;
            int h = pos & 1;
            float t = fmaf(qxs[k], p[0 + h], p[6 + h]);
            t = fmaf(qys[k], p[2 + h], t);
            t = fmaf(qzs[k], p[4 + h], t);
            if (t == best[k]) bi = min(bi, s_sidx[pos]);
        }
        g_idx[db * N_CONST + oq[k]] = bi;
        atomicAdd(&g_cnt[db * N_CONST + bi], 1);
    }
}

__global__ __launch_bounds__(FIN_TPB) void finalize_partial(const float* __restrict__ gts,
                                                            const float* __restrict__ preds) {
    __shared__ float ssum[FIN_TPB];
    const int e = blockIdx.x * FIN_TPB + threadIdx.x;
    const int db = e / N_CONST;
    const int q  = e - db * N_CONST;
    const int b  = db & (B_CONST - 1);
    const int dir = db >> 2;
    const float* qptr = (dir == 0) ? gts : preds;
    const float* rptr = (dir == 0) ? preds : gts;
    const float* qb = qptr + (long)b * N_CONST * 3;
    const float* rb = rptr + (long)b * N_CONST * 3;

    int id = g_idx[e];
    float dx = qb[3 * q + 0] - rb[3 * id + 0];
    float dy = qb[3 * q + 1] - rb[3 * id + 1];
    float dz = qb[3 * q + 2] - rb[3 * id + 2];
    float d  = dx * dx + dy * dy + dz * dz;
    float c  = (float)g_cnt[db * N_CONST + id];
    float acc = 1.0f - expf(-d) / (c + 1e-6f);   // ALPHA=1, N_LAMBDA=1, frac=1

    ssum[threadIdx.x] = acc;
    __syncthreads();
    for (int off = FIN_TPB / 2; off > 0; off >>= 1) {
        if (threadIdx.x < off) ssum[threadIdx.x] += ssum[threadIdx.x + off];
        __syncthreads();
    }
    if (threadIdx.x == 0) g_part[blockIdx.x] = ssum[0];
}

__global__ void finalize_final(float* __restrict__ out) {
    int b = threadIdx.x;
    if (b >= B_CONST) return;
    float s = 0.0f;
    #pragma unroll
    for (int dir = 0; dir < 2; dir++) {
        int db = dir * B_CONST + b;
        #pragma unroll
        for (int c = 0; c < FIN_CPD; c++)
            s += g_part[db * FIN_CPD + c];
    }
    out[b] = s / (2.0f * (float)N_CONST);
}

extern "C" void kernel_launch(void* const* d_in, const int* in_sizes, int n_in,
                              void* d_out, int out_size) {
    const float* gts   = (const float*)d_in[0];
    const float* preds = (const float*)d_in[1];
    float* out = (float*)d_out;

    cudaFuncSetAttribute(sort_kernel, cudaFuncAttributeMaxDynamicSharedMemorySize, SORT_SMEM);
    cudaFuncSetAttribute(nn_kernel, cudaFuncAttributeMaxDynamicSharedMemorySize, NN_SMEM);

    sort_kernel<<<NCLOUD, 512, SORT_SMEM>>>(gts, preds);
    nn_kernel<<<dim3(QCHUNKS, 2 * B_CONST), TPB, NN_SMEM>>>(gts, preds);
    finalize_partial<<<FIN_BLOCKS, FIN_TPB>>>(gts, preds);
    finalize_final<<<1, 32>>>(out);
}

// round 11
// speedup vs baseline: 1.5001x; 1.5001x over previous
#include <cuda_runtime.h>
#include <math_constants.h>

// Density-aware Chamfer loss, B=4, N=8192, 3D fp32.
// R11: parallel deterministic x-sort + outward pruned sweep on the R2 engine.
//  sort_kernel      : per cloud (8 blocks x 512 thr): stable counting sort by
//                     x-bin. Ranks via per-chunk match_any (stable), [chunk][bin]
//                     u8 count matrix, per-bin chunk prefix, parallel scatter.
//                     Deterministic. Also zeroes g_cnt.
//  nn_kernel        : sorted ref cloud in smem (jj-interleaved) + orig idx +
//                     monotone group x-bounds (x[32g], x[32g+31]). Queries in
//                     sorted order. Home-range init, then outward sweep with
//                     warp-vote early exit (inclusive compare + margin).
//                     Packed fma.rn.f32x2 body (bit-exact with rescan).
//                     Winning-group rescan -> min ORIGINAL index among ties.
//  finalize_partial : 256-block gather/exp/weight partial sums
//  finalize_final   : fixed-order merge -> out[b]

#define B_CONST   4
#define N_CONST   8192
#define NCLOUD    8
#define NBINS     256
#define NCHUNKS   (N_CONST / 32)       // 256

#define TPB       256
#define QPT       2
#define QPC       (TPB * QPT)          // 512 queries / CTA
#define QCHUNKS   (N_CONST / QPC)      // 16
#define GROUP     32
#define JPG       (GROUP / 2)          // 16
#define NGROUPS   (N_CONST / GROUP)    // 256

#define FIN_TPB   256
#define FIN_BLOCKS (2 * B_CONST * N_CONST / FIN_TPB)  // 256
#define FIN_CPD   (N_CONST / FIN_TPB)                 // 32

// sort smem: pts 131072 + cnt 65536 + rank 8192 + hist 1024 + base 1024
#define SORT_SMEM (131072 + 65536 + 8192 + 1024 + 1024)   // 206848
// nn smem: tile 32768f + sidx 8192i + glo 256f + ghi 256f
#define NN_SMEM   ((32768 + 8192 + 256 + 256) * 4)        // 165888

__device__ float4 g_sorted[NCLOUD * N_CONST];
__device__ int    g_sidx  [NCLOUD * N_CONST];
__device__ int    g_idx   [2 * B_CONST * N_CONST];
__device__ int    g_cnt   [2 * B_CONST * N_CONST];
__device__ float  g_part  [FIN_BLOCKS];

__device__ __forceinline__ int bin_of(float x) {
    int bi = (int)floorf((x + 5.2f) * (256.0f / 10.4f));
    return min(max(bi, 0), NBINS - 1);
}

// cloud 0..3 = gts[b], cloud 4..7 = preds[b]
__global__ __launch_bounds__(512, 1) void sort_kernel(const float* __restrict__ gts,
                                                      const float* __restrict__ preds) {
    extern __shared__ char sm_raw[];
    float4*        s_pts  = (float4*)sm_raw;                          // [8192]
    unsigned char* s_cnt  = (unsigned char*)(sm_raw + 131072);        // [chunk][bin]
    unsigned char* s_rank = (unsigned char*)(sm_raw + 131072 + 65536);// [8192]
    int*           s_hist = (int*)(sm_raw + 131072 + 65536 + 8192);   // [256]
    int*           s_base = s_hist + NBINS;                           // [256]

    const int tid  = threadIdx.x;
    const int cloud = blockIdx.x;
    const float* src = (cloud < 4) ? gts + (long)cloud * N_CONST * 3
                                   : preds + (long)(cloud - 4) * N_CONST * 3;

    for (int i = tid; i < N_CONST; i += 512) g_cnt[cloud * N_CONST + i] = 0;
    for (int i = tid; i < (NCHUNKS * NBINS) / 4; i += 512) ((int*)s_cnt)[i] = 0;
    for (int i = tid; i < N_CONST; i += 512) {
        float x = src[3 * i], y = src[3 * i + 1], z = src[3 * i + 2];
        s_pts[i] = make_float4(x, y, z, x * x + y * y + z * z);
    }
    __syncthreads();

    // per-chunk stable ranks + per-chunk-bin counts
    {
        const int w = tid >> 5, lane = tid & 31;
        for (int cc = 0; cc < NCHUNKS / 16; cc++) {
            int c = w * (NCHUNKS / 16) + cc;
            int i = c * 32 + lane;
            int bi = bin_of(s_pts[i].x);
            unsigned mask = __match_any_sync(0xffffffffu, bi);
            s_rank[i] = (unsigned char)__popc(mask & ((1u << lane) - 1u));
            if ((int)(__ffs(mask) - 1) == lane)
                s_cnt[c * NBINS + bi] = (unsigned char)__popc(mask);
        }
    }
    __syncthreads();

    // per-bin exclusive prefix over chunks (thread b owns bin b); totals -> hist
    if (tid < NBINS) {
        int run = 0;
        for (int c = 0; c < NCHUNKS; c++) {
            int v = s_cnt[c * NBINS + tid];
            s_cnt[c * NBINS + tid] = (unsigned char)run;
            run += v;
        }
        s_hist[tid] = run;
    }
    __syncthreads();
    if (tid == 0) {
        int run = 0;
        for (int bb = 0; bb < NBINS; bb++) { s_base[bb] = run; run += s_hist[bb]; }
    }
    __syncthreads();

    // parallel deterministic scatter
    for (int i = tid; i < N_CONST; i += 512) {
        float4 p = s_pts[i];
        int bi = bin_of(p.x);
        int pos = s_base[bi] + (int)s_cnt[(i >> 5) * NBINS + bi] + (int)s_rank[i];
        g_sorted[cloud * N_CONST + pos] = p;
        g_sidx[cloud * N_CONST + pos] = i;
    }
}

// Packed body: identical math to R2 (bit-exact with rescan).
#define NN_BODY(G)                                                              \
    {                                                                           \
        const float* gb = s_tile + (G) * (JPG * 8);                             \
        float mE0 = CUDART_INF_F, mO0 = CUDART_INF_F;                           \
        float mE1 = CUDART_INF_F, mO1 = CUDART_INF_F;                           \
        _Pragma("unroll")                                                       \
        for (int jj = 0; jj < JPG; jj++) {                                      \
            ulonglong2 A  = *(const ulonglong2*)(gb + jj * 8);                  \
            ulonglong2 Bv = *(const ulonglong2*)(gb + jj * 8 + 4);              \
            float tlo, thi;                                                     \
            asm("{\n\t.reg .b64 t;\n\t"                                         \
                "fma.rn.f32x2 t, %2, %3, %4;\n\t"                               \
                "fma.rn.f32x2 t, %5, %6, t;\n\t"                                \
                "fma.rn.f32x2 t, %7, %8, t;\n\t"                                \
                "mov.b64 {%0, %1}, t;\n\t}"                                     \
                : "=f"(tlo), "=f"(thi)                                          \
                : "l"(qx2[0]), "l"(A.x), "l"(Bv.y),                             \
                  "l"(qy2[0]), "l"(A.y), "l"(qz2[0]), "l"(Bv.x));               \
            mE0 = fminf(mE0, tlo); mO0 = fminf(mO0, thi);                       \
            asm("{\n\t.reg .b64 t;\n\t"                                         \
                "fma.rn.f32x2 t, %2, %3, %4;\n\t"                               \
                "fma.rn.f32x2 t, %5, %6, t;\n\t"                                \
                "fma.rn.f32x2 t, %7, %8, t;\n\t"                                \
                "mov.b64 {%0, %1}, t;\n\t}"                                     \
                : "=f"(tlo), "=f"(thi)                                          \
                : "l"(qx2[1]), "l"(A.x), "l"(Bv.y),                             \
                  "l"(qy2[1]), "l"(A.y), "l"(qz2[1]), "l"(Bv.x));               \
            mE1 = fminf(mE1, tlo); mO1 = fminf(mO1, thi);                       \
        }                                                                       \
        float m0 = fminf(mE0, mO0);                                             \
        if (m0 < best[0]) { best[0] = m0; gidw[0] = (G); bestd[0] = m0 + cc[0]; } \
        float m1 = fminf(mE1, mO1);                                             \
        if (m1 < best[1]) { best[1] = m1; gidw[1] = (G); bestd[1] = m1 + cc[1]; } \
    }

// db = dir*B + b.  dir 0: queries = gts, refs = preds. dir 1: swapped.
__global__ __launch_bounds__(TPB, 1) void nn_kernel() {
    extern __shared__ float sm[];
    float* s_tile = sm;                         // 32768 floats, jj-interleaved
    int*   s_sidx = (int*)(sm + 32768);         // 8192 orig indices
    float* s_glo  = sm + 32768 + 8192;          // 256 (monotone non-decreasing)
    float* s_ghi  = s_glo + NGROUPS;            // 256 (monotone non-decreasing)

    const int tid = threadIdx.x;
    const int db  = blockIdx.y;
    const int b   = db & 3;
    const int dir = db >> 2;
    const int qc  = (dir == 0) ? b : 4 + b;
    const int rc  = (dir == 0) ? 4 + b : b;
    const float4* gr  = g_sorted + rc * N_CONST;
    const int*    gri = g_sidx   + rc * N_CONST;
    const float4* gq  = g_sorted + qc * N_CONST;
    const int*    gqi = g_sidx   + qc * N_CONST;

    for (int j = tid; j < N_CONST; j += TPB) {
        float4 p = gr[j];
        int jj = j >> 1, h = j & 1;
        float* pp = s_tile + jj * 8;
        pp[0 + h] = p.x; pp[2 + h] = p.y; pp[4 + h] = p.z; pp[6 + h] = p.w;
        s_sidx[j] = gri[j];
    }
    __syncthreads();
    // group bounds: sorted => glo = x[32g], ghi = x[32g+31]
    if (tid < NGROUPS) {
        int p0 = tid * GROUP, p1 = tid * GROUP + GROUP - 1;
        s_glo[tid] = s_tile[(p0 >> 1) * 8 + (p0 & 1)];
        s_ghi[tid] = s_tile[(p1 >> 1) * 8 + (p1 & 1)];
    }
    __syncthreads();

    float qx[QPT], cc[QPT], qxs[QPT], qys[QPT], qzs[QPT];
    unsigned long long qx2[QPT], qy2[QPT], qz2[QPT];
    float best[QPT], bestd[QPT];
    int gidw[QPT], oq[QPT], ghome[QPT];

    #pragma unroll
    for (int k = 0; k < QPT; k++) {
        int qpos = blockIdx.x * QPC + tid * QPT + k;   // warp: 64 sorted-adjacent queries
        float4 qp = gq[qpos];
        oq[k] = gqi[qpos];
        qx[k] = qp.x; cc[k] = qp.w;
        qxs[k] = -2.0f * qp.x; qys[k] = -2.0f * qp.y; qzs[k] = -2.0f * qp.z;
        asm("mov.b64 %0, {%1, %1};" : "=l"(qx2[k]) : "f"(qxs[k]));
        asm("mov.b64 %0, {%1, %1};" : "=l"(qy2[k]) : "f"(qys[k]));
        asm("mov.b64 %0, {%1, %1};" : "=l"(qz2[k]) : "f"(qzs[k]));
        best[k] = CUDART_INF_F; bestd[k] = CUDART_INF_F; gidw[k] = 0;
        int lo = 0, hi = NGROUPS - 1;
        #pragma unroll
        for (int it = 0; it < 8; it++) {
            int mid = (lo + hi + 1) >> 1;
            if (s_glo[mid] <= qx[k]) lo = mid; else hi = mid - 1;
        }
        ghome[k] = lo;
    }

    // warp-uniform home range
    int gmn = min(ghome[0], ghome[1]);
    int gmx = max(ghome[0], ghome[1]);
    #pragma unroll
    for (int o = 16; o; o >>= 1) {
        gmn = min(gmn, __shfl_xor_sync(0xffffffffu, gmn, o));
        gmx = max(gmx, __shfl_xor_sync(0xffffffffu, gmx, o));
    }
    for (int g = gmn; g <= gmx; g++) NN_BODY(g);

    // right sweep: glo monotone non-decreasing & >= qx beyond home => first
    // all-lane prune implies all later groups pruned (early exit exact).
    for (int g = gmx + 1; g < NGROUPS; g++) {
        float e0 = s_glo[g] - qx[0];
        float e1 = s_glo[g] - qx[1];
        bool need = (e0 * e0 <= bestd[0] * 1.000002f + 1e-7f)
                 || (e1 * e1 <= bestd[1] * 1.000002f + 1e-7f);
        if (!__any_sync(0xffffffffu, need)) break;
        NN_BODY(g);
    }
    // left sweep: ghi monotone, <= qx below home.
    for (int g = gmn - 1; g >= 0; g--) {
        float e0 = qx[0] - s_ghi[g];
        float e1 = qx[1] - s_ghi[g];
        bool need = (e0 * e0 <= bestd[0] * 1.000002f + 1e-7f)
                 || (e1 * e1 <= bestd[1] * 1.000002f + 1e-7f);
        if (!__any_sync(0xffffffffu, need)) break;
        NN_BODY(g);
    }

    // rescan winning group: bit-exact recompute, min ORIGINAL index among ties
    #pragma unroll
    for (int k = 0; k < QPT; k++) {
        const int base = gidw[k] * GROUP;
        int bi = 0x7fffffff;
        #pragma unroll 8
        for (int j = 0; j < GROUP; j++) {
            int pos = base + j;
            const float* p = s_tile + (pos >> 1) * 8;
            int h = pos & 1;
            float t = fmaf(qxs[k], p[0 + h], p[6 + h]);
            t = fmaf(qys[k], p[2 + h], t);
            t = fmaf(qzs[k], p[4 + h], t);
            if (t == best[k]) bi = min(bi, s_sidx[pos]);
        }
        g_idx[db * N_CONST + oq[k]] = bi;
        atomicAdd(&g_cnt[db * N_CONST + bi], 1);
    }
}

__global__ __launch_bounds__(FIN_TPB) void finalize_partial(const float* __restrict__ gts,
                                                            const float* __restrict__ preds) {
    __shared__ float ssum[FIN_TPB];
    const int e = blockIdx.x * FIN_TPB + threadIdx.x;
    const int db = e / N_CONST;
    const int q  = e - db * N_CONST;
    const int b  = db & (B_CONST - 1);
    const int dir = db >> 2;
    const float* qptr = (dir == 0) ? gts : preds;
    const float* rptr = (dir == 0) ? preds : gts;
    const float* qb = qptr + (long)b * N_CONST * 3;
    const float* rb = rptr + (long)b * N_CONST * 3;

    int id = g_idx[e];
    float dx = qb[3 * q + 0] - rb[3 * id + 0];
    float dy = qb[3 * q + 1] - rb[3 * id + 1];
    float dz = qb[3 * q + 2] - rb[3 * id + 2];
    float d  = dx * dx + dy * dy + dz * dz;
    float c  = (float)g_cnt[db * N_CONST + id];
    float acc = 1.0f - expf(-d) / (c + 1e-6f);   // ALPHA=1, N_LAMBDA=1, frac=1

    ssum[threadIdx.x] = acc;
    __syncthreads();
    for (int off = FIN_TPB / 2; off > 0; off >>= 1) {
        if (threadIdx.x < off) ssum[threadIdx.x] += ssum[threadIdx.x + off];
        __syncthreads();
    }
    if (threadIdx.x == 0) g_part[blockIdx.x] = ssum[0];
}

__global__ void finalize_final(float* __restrict__ out) {
    int b = threadIdx.x;
    if (b >= B_CONST) return;
    float s = 0.0f;
    #pragma unroll
    for (int dir = 0; dir < 2; dir++) {
        int db = dir * B_CONST + b;
        #pragma unroll
        for (int c = 0; c < FIN_CPD; c++)
            s += g_part[db * FIN_CPD + c];
    }
    out[b] = s / (2.0f * (float)N_CONST);
}

extern "C" void kernel_launch(void* const* d_in, const int* in_sizes, int n_in,
                              void* d_out, int out_size) {
    const float* gts   = (const float*)d_in[0];
    const float* preds = (const float*)d_in[1];
    float* out = (float*)d_out;

    cudaFuncSetAttribute(sort_kernel, cudaFuncAttributeMaxDynamicSharedMemorySize, SORT_SMEM);
    cudaFuncSetAttribute(nn_kernel, cudaFuncAttributeMaxDynamicSharedMemorySize, NN_SMEM);

    sort_kernel<<<NCLOUD, 512, SORT_SMEM>>>(gts, preds);
    nn_kernel<<<dim3(QCHUNKS, 2 * B_CONST), TPB, NN_SMEM>>>();
    finalize_partial<<<FIN_BLOCKS, FIN_TPB>>>(gts, preds);
    finalize_final<<<1, 32>>>(out);
}